// round 15
// baseline (speedup 1.0000x reference)
#include <cuda_runtime.h>
#include <cuda_fp16.h>
#include <math.h>
#include <stdint.h>

#define TT 4096
#define DD 1024
#define FF 4096
#define EE 8
#define SS 2048
#define HH 16
#define DK 64
#define DP (DD/2)

// ---------------- scratch ----------------
__device__ uint2    g_xhl[TT * DP];                       // x packed (hi,lo)
__device__ uint2    g_wqkvhl[3u * DP * DD];               // [z][K/2][N] (hi,lo)
__device__ uint2    g_wohl[DP * DD];
__device__ uint2    g_qkhl[2u * TT * DP];                 // Q,K packed
__device__ float    g_v[TT * DD];
__device__ uint2    g_vhl[(TT / 2) * DD];                 // V packed (pairs along token)
__device__ uint2    g_cthl[TT * DP];                      // ctx packed
__device__ float    g_res1[TT * DD];
__device__ float    g_x1[TT * DD];
__device__ uint32_t g_x1h[TT * DP];
__device__ uint32_t g_w1h[(size_t)EE * DP * FF];          // [E][D/2][F] plain
__device__ uint32_t g_w2h[(size_t)EE * (FF / 2) * DD];    // [E][F/2][D] plain
__device__ uint32_t g_acth[2u * TT * (FF / 2)];
__device__ float    g_acc[TT * DD];
__device__ float    g_gatew[2 * TT];
__device__ int      g_counts[EE];
__device__ int      g_list[EE * TT];
__device__ float    g_bqkv[3 * DD];

// ---------------- helpers ----------------
__device__ __forceinline__ uint32_t smem_u32(const void* p) {
    uint32_t a;
    asm("{ .reg .u64 t; cvta.to.shared.u64 t, %1; cvt.u32.u64 %0, t; }" : "=r"(a) : "l"(p));
    return a;
}
__device__ __forceinline__ void cp16(uint32_t dst, const void* src) {
    asm volatile("cp.async.cg.shared.global [%0], [%1], 16;" :: "r"(dst), "l"(src));
}
__device__ __forceinline__ void cp16z(uint32_t dst, const void* src, int sz) {
    asm volatile("cp.async.cg.shared.global [%0], [%1], 16, %2;" :: "r"(dst), "l"(src), "r"(sz));
}
__device__ __forceinline__ void cp_commit() { asm volatile("cp.async.commit_group;"); }
__device__ __forceinline__ void cp_wait1() { asm volatile("cp.async.wait_group 1;" ::: "memory"); }
__device__ __forceinline__ void cp_wait0() { asm volatile("cp.async.wait_group 0;" ::: "memory"); }

__device__ __forceinline__ void mma_f16(float* d, const uint32_t* a, const uint32_t* b) {
    asm volatile(
        "mma.sync.aligned.m16n8k16.row.col.f32.f16.f16.f32 "
        "{%0,%1,%2,%3}, {%4,%5,%6,%7}, {%8,%9}, {%0,%1,%2,%3};"
        : "+f"(d[0]), "+f"(d[1]), "+f"(d[2]), "+f"(d[3])
        : "r"(a[0]), "r"(a[1]), "r"(a[2]), "r"(a[3]), "r"(b[0]), "r"(b[1]));
}
__device__ __forceinline__ uint32_t packh2(float a, float b) {
    __half2 h = __floats2half2_rn(a, b);
    return *reinterpret_cast<uint32_t*>(&h);
}
__device__ __forceinline__ void split2(float a, float b, uint32_t& hi, uint32_t& lo) {
    __half2 h = __floats2half2_rn(a, b);
    float2 f = __half22float2(h);
    __half2 l = __floats2half2_rn(a - f.x, b - f.y);
    hi = *reinterpret_cast<uint32_t*>(&h);
    lo = *reinterpret_cast<uint32_t*>(&l);
}
__device__ __forceinline__ float fexp(float x) {
    float t = fmaxf(x * 1.4426950408889634f, -126.0f);
    float fl = floorf(t);
    float f = t - fl;
    float p = 1.53998500e-4f;
    p = fmaf(p, f, 1.33335581e-3f);
    p = fmaf(p, f, 9.61817007e-3f);
    p = fmaf(p, f, 5.55041087e-2f);
    p = fmaf(p, f, 2.40226507e-1f);
    p = fmaf(p, f, 6.93147182e-1f);
    p = fmaf(p, f, 1.0f);
    return __int_as_float(__float_as_int(p) + (((int)fl) << 23));
}

// ---------------- pack kernels ----------------
// interleaved (hi,lo) row-pair pack; total pairs = grid*1024*4
__global__ void pack_rows2i_kernel(const float* __restrict__ in, uint2* __restrict__ ohl,
                                   int shift, int total)
{
    int t0 = (blockIdx.x * 256 + threadIdx.x) * 4;
    int stride = gridDim.x * 1024;
    int C = 1 << shift;
    float4 a[4], b[4];
#pragma unroll
    for (int u = 0; u < 4; u++) {
        int i = t0 + u * stride;
        size_t ai = (size_t)i + ((size_t)(i >> shift) << shift);
        a[u] = *(const float4*)(in + ai);
        b[u] = *(const float4*)(in + ai + C);
    }
#pragma unroll
    for (int u = 0; u < 4; u++) {
        int i = t0 + u * stride;
        uint32_t h0, l0, h1, l1, h2, l2, h3, l3;
        split2(a[u].x, b[u].x, h0, l0);
        split2(a[u].y, b[u].y, h1, l1);
        split2(a[u].z, b[u].z, h2, l2);
        split2(a[u].w, b[u].w, h3, l3);
        uint4* o = (uint4*)&ohl[i];
        o[0] = make_uint4(h0, l0, h1, l1);
        o[1] = make_uint4(h2, l2, h3, l3);
    }
}

// plain fp16 row-pair pack (FFN weights)
__global__ void pack_rows2_kernel(const float* __restrict__ in, uint32_t* __restrict__ oh,
                                  int shift, int total)
{
    int t0 = (blockIdx.x * 256 + threadIdx.x) * 4;
    int stride = gridDim.x * 1024;
    int C = 1 << shift;
    float4 a[4], b[4];
#pragma unroll
    for (int u = 0; u < 4; u++) {
        int i = t0 + u * stride;
        size_t ai = (size_t)i + ((size_t)(i >> shift) << shift);
        a[u] = *(const float4*)(in + ai);
        b[u] = *(const float4*)(in + ai + C);
    }
#pragma unroll
    for (int u = 0; u < 4; u++) {
        int i = t0 + u * stride;
        oh[i + 0] = packh2(a[u].x, b[u].x);
        oh[i + 1] = packh2(a[u].y, b[u].y);
        oh[i + 2] = packh2(a[u].z, b[u].z);
        oh[i + 3] = packh2(a[u].w, b[u].w);
    }
}

__global__ void pack_cols_kernel(const float* __restrict__ in, uint2* __restrict__ ohl)
{
    int r = blockIdx.x;
    int c = threadIdx.x * 4;
    float4 a = *(const float4*)(in + (size_t)r * DD + c);
    uint32_t h0, l0, h1, l1;
    split2(a.x, a.y, h0, l0);
    split2(a.z, a.w, h1, l1);
    *(uint4*)&ohl[(size_t)r * DP + (c >> 1)] = make_uint4(h0, l0, h1, l1);
}

__global__ void concat_bias_kernel(const float* bq, const float* bk, const float* bv,
                                   float* out)
{
    int i = blockIdx.x * 256 + threadIdx.x;
    if (i < DD) { out[i] = bq[i]; out[DD + i] = bk[i]; out[2 * DD + i] = bv[i]; }
}

__global__ void zero_acc_kernel(float* acc)
{
    ((float4*)acc)[blockIdx.x * 256 + threadIdx.x] = make_float4(0.f, 0.f, 0.f, 0.f);
}

// ========== fp16 2-way-split GEMM (interleaved planes): QKV + O ==========
#define AP2 20                 // uint2 per A row
#define ASTG2 (128 * AP2)      // 2560 uint2
#define BP2 136                // uint2 per B (k) row
#define BSTG2 (16 * BP2)       // 2176 uint2
#define SPLIT_SMEM ((2 * ASTG2 + 2 * BSTG2) * 8)   // 75776 B

__global__ void __launch_bounds__(256)
mm_half_split(const uint2* __restrict__ Ahl,
              const uint2* __restrict__ Bbase,     // [Z][K/2][N]
              const float* __restrict__ biasB,
              const float* __restrict__ resid,
              uint2* __restrict__ OHL,             // [z][M][N/2] for z<fp32z
              float* __restrict__ OF,
              int K, int N, int fp32z)
{
    int z = blockIdx.z;
    int m0 = blockIdx.y * 128;
    int n0 = blockIdx.x * 128;
    int Kp = K >> 1;
    const uint2* Bhl = Bbase + (size_t)z * Kp * N;
    const float* bias = biasB + (size_t)z * N;

    extern __shared__ uint2 sm2[];
    uint2* sA = sm2;                     // [2][128][AP2]
    uint2* sB = sm2 + 2 * ASTG2;         // [2][16][BP2]
    uint32_t uA = smem_u32(sA), uB = smem_u32(sB);

    int tid = threadIdx.x;

    auto load_stage = [&](int s, int kp0) {
#pragma unroll
        for (int i = 0; i < 8; i++) {
            int c = (tid + (i & 3) * 256) & 1023;
            if (i < 4) {       // A: 128 rows x 8 chunks (16B = 2 uint2)
                int row = c >> 3, seg = c & 7;
                cp16(uA + (uint32_t)(s * ASTG2 + row * AP2 + seg * 2) * 8,
                     Ahl + (size_t)(m0 + row) * Kp + kp0 + seg * 2);
            } else {           // B: 16 k-rows x 64 chunks
                int row = c >> 6, seg = c & 63;
                cp16(uB + (uint32_t)(s * BSTG2 + row * BP2 + seg * 2) * 8,
                     Bhl + (size_t)(kp0 + row) * N + n0 + seg * 2);
            }
        }
    };

    int NC = K >> 5;
    load_stage(0, 0); cp_commit();
    load_stage(1, 16); cp_commit();

    int w = tid >> 5, lane = tid & 31;
    int wm = w & 3, wn = w >> 2;
    int g = lane >> 2, ct = lane & 3;

    float acc[2][8][4];
#pragma unroll
    for (int mi = 0; mi < 2; mi++)
#pragma unroll
        for (int ni = 0; ni < 8; ni++)
#pragma unroll
            for (int j = 0; j < 4; j++) acc[mi][ni][j] = 0.f;

    for (int i = 0; i < NC; i++) {
        if (i + 1 < NC) cp_wait1(); else cp_wait0();
        __syncthreads();
        const uint2* Aw = sA + (i & 1) * ASTG2;
        const uint2* Bw = sB + (i & 1) * BSTG2;
#pragma unroll
        for (int ks = 0; ks < 2; ks++) {
            int kb = ks * 8;
            uint32_t ah[2][4], al[2][4];
#pragma unroll
            for (int mi = 0; mi < 2; mi++) {
                int rb = wm * 32 + mi * 16;
                uint2 p0 = Aw[(rb + g) * AP2 + kb + ct];
                uint2 p1 = Aw[(rb + g + 8) * AP2 + kb + ct];
                uint2 p2 = Aw[(rb + g) * AP2 + kb + ct + 4];
                uint2 p3 = Aw[(rb + g + 8) * AP2 + kb + ct + 4];
                ah[mi][0] = p0.x; al[mi][0] = p0.y;
                ah[mi][1] = p1.x; al[mi][1] = p1.y;
                ah[mi][2] = p2.x; al[mi][2] = p2.y;
                ah[mi][3] = p3.x; al[mi][3] = p3.y;
            }
#pragma unroll
            for (int ni = 0; ni < 8; ni++) {
                int n = wn * 64 + ni * 8 + g;
                uint2 q0 = Bw[(kb + ct) * BP2 + n];
                uint2 q1 = Bw[(kb + ct + 4) * BP2 + n];
                uint32_t bh[2] = { q0.x, q1.x };
                uint32_t bl[2] = { q0.y, q1.y };
#pragma unroll
                for (int mi = 0; mi < 2; mi++) {
                    mma_f16(acc[mi][ni], ah[mi], bh);
                    mma_f16(acc[mi][ni], ah[mi], bl);
                    mma_f16(acc[mi][ni], al[mi], bh);
                }
            }
        }
        __syncthreads();
        if (i + 2 < NC) { load_stage(i & 1, (i + 2) * 16); cp_commit(); }
    }

    bool fp32o = (z == fp32z);
#pragma unroll
    for (int mi = 0; mi < 2; mi++) {
#pragma unroll
        for (int h = 0; h < 2; h++) {
            int m = m0 + wm * 32 + mi * 16 + g + h * 8;
#pragma unroll
            for (int ni = 0; ni < 8; ni++) {
                int col = n0 + wn * 64 + ni * 8 + 2 * ct;
                float v0 = acc[mi][ni][2 * h + 0] + bias[col];
                float v1 = acc[mi][ni][2 * h + 1] + bias[col + 1];
                if (fp32o) {
                    if (resid) {
                        v0 += resid[(size_t)m * N + col];
                        v1 += resid[(size_t)m * N + col + 1];
                    }
                    *(float2*)&OF[(size_t)m * N + col] = make_float2(v0, v1);
                } else {
                    uint32_t hh, ll;
                    split2(v0, v1, hh, ll);
                    size_t o = (size_t)z * TT * (N >> 1) + (size_t)m * (N >> 1) + (col >> 1);
                    OHL[o] = make_uint2(hh, ll);
                }
            }
        }
    }
}

// ========== plain fp16 GEMM (gathered A) — 3-stage pipeline ==========
#define APF 20
#define ASTGF (128 * APF)   // u32
#define BPF 136
#define BSTGF (16 * BPF)    // u32
#define PLAIN_SMEM ((3 * ASTGF + 3 * BSTGF) * 4)   // 56832 B

__global__ void __launch_bounds__(256)
mm_half_plain(const uint32_t* __restrict__ Ah,
              const uint32_t* __restrict__ WhB,
              const float* __restrict__ biasB,
              uint32_t* __restrict__ OH,
              float* __restrict__ ACC,
              const float* __restrict__ gatew,
              int K, int N,
              const int* __restrict__ listB, const int* __restrict__ counts,
              int a_shift, int actmode)
{
    int e = blockIdx.z;
    const int* list = listB + e * TT;
    int Me = counts[e];
    int m0 = blockIdx.y * 128;
    if (m0 >= Me) return;
    int n0 = blockIdx.x * 128;
    int Kp = K >> 1;
    const uint32_t* Wh = WhB + (size_t)e * Kp * N;
    const float* bias = biasB + (size_t)e * N;

    extern __shared__ uint32_t smu[];
    uint32_t* sAh = smu;
    uint32_t* sBh = smu + 3 * ASTGF;
    uint32_t uAh = smem_u32(sAh), uBh = smem_u32(sBh);

    __shared__ int rows_s[128];
    __shared__ int crows_s[128];
    int tid = threadIdx.x;
    if (tid < 128) {
        int m = m0 + tid;
        int r = -1, cr = -1;
        if (m < Me) { int ent = list[m]; r = ent >> a_shift; cr = ent; }
        rows_s[tid] = r; crows_s[tid] = cr;
    }
    __syncthreads();

    auto load_stage = [&](int s, int kp0) {
#pragma unroll
        for (int i = 0; i < 4; i++) {
            int c = (tid + (i & 1) * 256) & 511;
            if (i < 2) {
                int row = c >> 2, seg = c & 3;
                int ar = rows_s[row];
                const uint32_t* src = (ar >= 0) ? Ah + (size_t)ar * Kp + kp0 + seg * 4 : Ah;
                cp16z(uAh + (uint32_t)(s * ASTGF + row * APF + seg * 4) * 4, src,
                      (ar >= 0) ? 16 : 0);
            } else {
                int prow = c >> 5, seg = c & 31;
                cp16(uBh + (uint32_t)(s * BSTGF + prow * BPF + seg * 4) * 4,
                     Wh + (size_t)(kp0 + prow) * N + n0 + seg * 4);
            }
        }
    };

    int NC = K >> 5;
    load_stage(0, 0); cp_commit();
    load_stage(1, 16); cp_commit();

    int w = tid >> 5, lane = tid & 31;
    int wm = w & 3, wn = w >> 2;
    int g = lane >> 2, ct = lane & 3;

    float acc[2][8][4];
#pragma unroll
    for (int mi = 0; mi < 2; mi++)
#pragma unroll
        for (int ni = 0; ni < 8; ni++)
#pragma unroll
            for (int j = 0; j < 4; j++) acc[mi][ni][j] = 0.f;

    for (int i = 0; i < NC; i++) {
        if (i + 1 < NC) cp_wait1(); else cp_wait0();
        __syncthreads();
        if (i + 2 < NC) { load_stage((i + 2) % 3, (i + 2) * 16); cp_commit(); }
        int sb = i % 3;
        const uint32_t* Ahw = sAh + sb * ASTGF;
        const uint32_t* Bhw = sBh + sb * BSTGF;
#pragma unroll
        for (int ks = 0; ks < 2; ks++) {
            int kb = ks * 8;
            uint32_t ah[2][4];
#pragma unroll
            for (int mi = 0; mi < 2; mi++) {
                int rb = wm * 32 + mi * 16;
                ah[mi][0] = Ahw[(rb + g) * APF + kb + ct];
                ah[mi][1] = Ahw[(rb + g + 8) * APF + kb + ct];
                ah[mi][2] = Ahw[(rb + g) * APF + kb + ct + 4];
                ah[mi][3] = Ahw[(rb + g + 8) * APF + kb + ct + 4];
            }
#pragma unroll
            for (int ni = 0; ni < 8; ni++) {
                int n = wn * 64 + ni * 8 + g;
                uint32_t bh[2] = { Bhw[(kb + ct) * BPF + n], Bhw[(kb + ct + 4) * BPF + n] };
#pragma unroll
                for (int mi = 0; mi < 2; mi++)
                    mma_f16(acc[mi][ni], ah[mi], bh);
            }
        }
    }

    int act = (actmode == 3) ? ((e & 1) ? 2 : 1) : actmode;
#pragma unroll
    for (int mi = 0; mi < 2; mi++) {
#pragma unroll
        for (int h = 0; h < 2; h++) {
            int rl = wm * 32 + mi * 16 + g + h * 8;
            int crow = crows_s[rl];
            if (crow < 0) continue;
            float wgt = OH ? 0.f : gatew[crow];
#pragma unroll
            for (int ni = 0; ni < 8; ni++) {
                int col = n0 + wn * 64 + ni * 8 + 2 * ct;
                float v0 = acc[mi][ni][2 * h + 0] + bias[col];
                float v1 = acc[mi][ni][2 * h + 1] + bias[col + 1];
                if (act == 1) {
                    v0 = 0.5f * v0 * (1.f + erff(v0 * 0.70710678118654752f));
                    v1 = 0.5f * v1 * (1.f + erff(v1 * 0.70710678118654752f));
                } else if (act == 2) {
                    v0 = v0 / (1.f + __expf(-v0));
                    v1 = v1 / (1.f + __expf(-v1));
                }
                if (OH) {
                    OH[(size_t)crow * (N >> 1) + (col >> 1)] = packh2(v0, v1);
                } else {
                    float* arow = ACC + (size_t)(crow >> 1) * N + col;
                    atomicAdd(arow, wgt * v0);
                    atomicAdd(arow + 1, wgt * v1);
                }
            }
        }
    }
}

// ========== fp16-split flash attention (interleaved planes) ==========
// smem uint2 offsets: Q 0, K 2304, V 4608, P 6912; pitches Q/K/P 36, V 72.
#define AQOFF 0
#define AKOFF 2304
#define AVOFF 4608
#define APOFF 6912
#define ATTN_SMEM (9216 * 8)   // 73728 B

__global__ void __launch_bounds__(256, 2)
attn_half_kernel(const uint2* __restrict__ Qhl, const uint2* __restrict__ Khl,
                 const uint2* __restrict__ Vhl, uint2* __restrict__ Chl)
{
    extern __shared__ uint2 sm2[];
    __shared__ float redm[128], reds[128];

    int qt = blockIdx.x, h = blockIdx.y, b = blockIdx.z;
    int tid = threadIdx.x;
    int w = tid >> 5, lane = tid & 31;
    int wm = w & 3, wn = w >> 2;
    int g = lane >> 2, ct = lane & 3;
    int r0 = wm * 16 + g, r1 = r0 + 8;

    int qglob = b * SS + qt * 64;

    uint32_t uQ = smem_u32(sm2 + AQOFF);
    uint32_t uK = smem_u32(sm2 + AKOFF);
    uint32_t uV = smem_u32(sm2 + AVOFF);

    // Q: 64 rows x 16 chunks (16B = 2 uint2)
#pragma unroll
    for (int i = 0; i < 4; i++) {
        int c = tid + i * 256;
        int row = c >> 4, seg = c & 15;
        cp16(uQ + (uint32_t)(row * 36 + seg * 2) * 8,
             Qhl + (size_t)(qglob + row) * DP + h * 32 + seg * 2);
    }
    cp_commit();

    float oacc[4][4];
#pragma unroll
    for (int ni = 0; ni < 4; ni++)
#pragma unroll
        for (int j = 0; j < 4; j++) oacc[ni][j] = 0.f;
    float mrun0 = -1e30f, mrun1 = -1e30f, lrun0 = 0.f, lrun1 = 0.f;

    const uint2* Qs = sm2 + AQOFF;
    const uint2* Ks = sm2 + AKOFF;
    const uint2* Vs = sm2 + AVOFF;
    uint2* Ps = sm2 + APOFF;

    for (int t = 0; t < SS / 64; t++) {
        int k0t = t * 64;
        __syncthreads();
        // K: 64 rows x 16 chunks
#pragma unroll
        for (int i = 0; i < 4; i++) {
            int c = tid + i * 256;
            int row = c >> 4, seg = c & 15;
            cp16(uK + (uint32_t)(row * 36 + seg * 2) * 8,
                 Khl + (size_t)(b * SS + k0t + row) * DP + h * 32 + seg * 2);
        }
        // V: 32 pair-rows x 32 chunks
#pragma unroll
        for (int i = 0; i < 4; i++) {
            int c = tid + i * 256;
            int row = c >> 5, seg = c & 31;
            cp16(uV + (uint32_t)(row * 72 + seg * 2) * 8,
                 Vhl + (size_t)((b * SS + k0t) / 2 + row) * DD + h * 64 + seg * 2);
        }
        cp_commit();
        cp_wait0();
        __syncthreads();

        // ---- S = Q K^T (fp16 split) ----
        float sacc[4][4];
#pragma unroll
        for (int ni = 0; ni < 4; ni++)
#pragma unroll
            for (int j = 0; j < 4; j++) sacc[ni][j] = 0.f;
#pragma unroll
        for (int ks = 0; ks < 4; ks++) {
            int kb = ks * 8;
            uint2 q0 = Qs[r0 * 36 + kb + ct];
            uint2 q1 = Qs[r1 * 36 + kb + ct];
            uint2 q2 = Qs[r0 * 36 + kb + ct + 4];
            uint2 q3 = Qs[r1 * 36 + kb + ct + 4];
            uint32_t ah[4] = { q0.x, q1.x, q2.x, q3.x };
            uint32_t al[4] = { q0.y, q1.y, q2.y, q3.y };
#pragma unroll
            for (int ni = 0; ni < 4; ni++) {
                int n = wn * 32 + ni * 8 + g;
                uint2 k0 = Ks[n * 36 + kb + ct];
                uint2 k1 = Ks[n * 36 + kb + ct + 4];
                uint32_t bh[2] = { k0.x, k1.x };
                uint32_t bl[2] = { k0.y, k1.y };
                mma_f16(sacc[ni], ah, bh);
                mma_f16(sacc[ni], ah, bl);
                mma_f16(sacc[ni], al, bh);
            }
        }
#pragma unroll
        for (int ni = 0; ni < 4; ni++)
#pragma unroll
            for (int j = 0; j < 4; j++) sacc[ni][j] *= 0.125f;

        // ---- online softmax ----
        float mx0 = -1e30f, mx1 = -1e30f;
#pragma unroll
        for (int ni = 0; ni < 4; ni++) {
            mx0 = fmaxf(mx0, fmaxf(sacc[ni][0], sacc[ni][1]));
            mx1 = fmaxf(mx1, fmaxf(sacc[ni][2], sacc[ni][3]));
        }
        mx0 = fmaxf(mx0, __shfl_xor_sync(~0u, mx0, 1));
        mx0 = fmaxf(mx0, __shfl_xor_sync(~0u, mx0, 2));
        mx1 = fmaxf(mx1, __shfl_xor_sync(~0u, mx1, 1));
        mx1 = fmaxf(mx1, __shfl_xor_sync(~0u, mx1, 2));
        if (ct == 0) { redm[wn * 64 + r0] = mx0; redm[wn * 64 + r1] = mx1; }
        __syncthreads();
        float mn0 = fmaxf(mrun0, fmaxf(redm[r0], redm[64 + r0]));
        float mn1 = fmaxf(mrun1, fmaxf(redm[r1], redm[64 + r1]));
        float c0 = fexp(mrun0 - mn0), c1 = fexp(mrun1 - mn1);
        mrun0 = mn0; mrun1 = mn1;
        float sum0 = 0.f, sum1 = 0.f;
#pragma unroll
        for (int ni = 0; ni < 4; ni++) {
            float p00 = fexp(sacc[ni][0] - mn0), p01 = fexp(sacc[ni][1] - mn0);
            float p10 = fexp(sacc[ni][2] - mn1), p11 = fexp(sacc[ni][3] - mn1);
            sum0 += p00 + p01; sum1 += p10 + p11;
            int pc = wn * 16 + ni * 4 + ct;
            uint32_t hh, ll;
            split2(p00, p01, hh, ll);
            Ps[r0 * 36 + pc] = make_uint2(hh, ll);
            split2(p10, p11, hh, ll);
            Ps[r1 * 36 + pc] = make_uint2(hh, ll);
        }
        sum0 += __shfl_xor_sync(~0u, sum0, 1);
        sum0 += __shfl_xor_sync(~0u, sum0, 2);
        sum1 += __shfl_xor_sync(~0u, sum1, 1);
        sum1 += __shfl_xor_sync(~0u, sum1, 2);
        if (ct == 0) { reds[wn * 64 + r0] = sum0; reds[wn * 64 + r1] = sum1; }
        __syncthreads();
        lrun0 = lrun0 * c0 + reds[r0] + reds[64 + r0];
        lrun1 = lrun1 * c1 + reds[r1] + reds[64 + r1];
#pragma unroll
        for (int ni = 0; ni < 4; ni++) {
            oacc[ni][0] *= c0; oacc[ni][1] *= c0;
            oacc[ni][2] *= c1; oacc[ni][3] *= c1;
        }

        // ---- O += P V (fp16 split) ----
#pragma unroll
        for (int ks = 0; ks < 4; ks++) {
            int kb = ks * 8;
            uint2 p0 = Ps[r0 * 36 + kb + ct];
            uint2 p1 = Ps[r1 * 36 + kb + ct];
            uint2 p2 = Ps[r0 * 36 + kb + ct + 4];
            uint2 p3 = Ps[r1 * 36 + kb + ct + 4];
            uint32_t ah[4] = { p0.x, p1.x, p2.x, p3.x };
            uint32_t al[4] = { p0.y, p1.y, p2.y, p3.y };
#pragma unroll
            for (int ni = 0; ni < 4; ni++) {
                int n = wn * 32 + ni * 8 + g;
                uint2 v0 = Vs[(kb + ct) * 72 + n];
                uint2 v1 = Vs[(kb + ct + 4) * 72 + n];
                uint32_t bh[2] = { v0.x, v1.x };
                uint32_t bl[2] = { v0.y, v1.y };
                mma_f16(oacc[ni], ah, bh);
                mma_f16(oacc[ni], ah, bl);
                mma_f16(oacc[ni], al, bh);
            }
        }
    }

    float inv0 = 1.f / lrun0, inv1 = 1.f / lrun1;
#pragma unroll
    for (int ni = 0; ni < 4; ni++) {
        int pc = h * 32 + wn * 16 + ni * 4 + ct;
        uint32_t hh, ll;
        split2(oacc[ni][0] * inv0, oacc[ni][1] * inv0, hh, ll);
        Chl[(size_t)(qglob + r0) * DP + pc] = make_uint2(hh, ll);
        split2(oacc[ni][2] * inv1, oacc[ni][3] * inv1, hh, ll);
        Chl[(size_t)(qglob + r1) * DP + pc] = make_uint2(hh, ll);
    }
}

// ---------------- layernorm ----------------
__global__ void ln_kernel(const float* __restrict__ in,
                          const float* __restrict__ gam,
                          const float* __restrict__ bet,
                          float* __restrict__ out, uint32_t* __restrict__ outh)
{
    __shared__ float ssum[8], ssum2[8];
    __shared__ float smean, srstd;
    int t = blockIdx.x;
    const float4* r = (const float4*)(in + (size_t)t * DD);
    float4 vv = r[threadIdx.x];
    float s = vv.x + vv.y + vv.z + vv.w;
    float s2 = vv.x * vv.x + vv.y * vv.y + vv.z * vv.z + vv.w * vv.w;
    int lane = threadIdx.x & 31, w = threadIdx.x >> 5;
#pragma unroll
    for (int o = 16; o; o >>= 1) {
        s += __shfl_xor_sync(~0u, s, o);
        s2 += __shfl_xor_sync(~0u, s2, o);
    }
    if (!lane) { ssum[w] = s; ssum2[w] = s2; }
    __syncthreads();
    if (threadIdx.x == 0) {
        float a = 0.f, bb = 0.f;
#pragma unroll
        for (int i = 0; i < 8; i++) { a += ssum[i]; bb += ssum2[i]; }
        float mean = a * (1.f / DD);
        float var = bb * (1.f / DD) - mean * mean;
        smean = mean; srstd = rsqrtf(var + 1e-5f);
    }
    __syncthreads();
    float4 g4 = ((const float4*)gam)[threadIdx.x];
    float4 b4 = ((const float4*)bet)[threadIdx.x];
    float m = smean, rs = srstd;
    float4 o4;
    o4.x = (vv.x - m) * rs * g4.x + b4.x;
    o4.y = (vv.y - m) * rs * g4.y + b4.y;
    o4.z = (vv.z - m) * rs * g4.z + b4.z;
    o4.w = (vv.w - m) * rs * g4.w + b4.w;
    ((float4*)(out + (size_t)t * DD))[threadIdx.x] = o4;
    if (outh) {
        outh[(size_t)t * DP + threadIdx.x * 2] = packh2(o4.x, o4.y);
        outh[(size_t)t * DP + threadIdx.x * 2 + 1] = packh2(o4.z, o4.w);
    }
}

// ---------------- gate ----------------
__global__ void zero_counts_kernel() {
    if (threadIdx.x < EE) g_counts[threadIdx.x] = 0;
}

__global__ void gate_kernel(const float* __restrict__ x1,
                            const float* __restrict__ gw,
                            const float* __restrict__ gb)
{
    int t = blockIdx.x * (blockDim.x / 32) + (threadIdx.x >> 5);
    int lane = threadIdx.x & 31;
    float acc[EE] = {};
    const float* xr = x1 + (size_t)t * DD;
    for (int d = lane; d < DD; d += 32) {
        float xv = xr[d];
        const float* grow = gw + (size_t)d * EE;
#pragma unroll
        for (int e = 0; e < EE; e++) acc[e] += xv * grow[e];
    }
#pragma unroll
    for (int e = 0; e < EE; e++)
#pragma unroll
        for (int o = 16; o; o >>= 1) acc[e] += __shfl_xor_sync(~0u, acc[e], o);
    if (lane == 0) {
#pragma unroll
        for (int e = 0; e < EE; e++) acc[e] += gb[e];
        float best = -1e30f; int bi = 0;
#pragma unroll
        for (int e = 0; e < EE; e++)
            if (acc[e] > best) { best = acc[e]; bi = e; }
        float best2 = -1e30f; int bi2 = 0;
#pragma unroll
        for (int e = 0; e < EE; e++)
            if (e != bi && acc[e] > best2) { best2 = acc[e]; bi2 = e; }
        float w0 = 1.f / (1.f + __expf(best2 - best));
        g_gatew[2 * t] = w0;
        g_gatew[2 * t + 1] = 1.f - w0;
        int p0 = atomicAdd(&g_counts[bi], 1);
        g_list[bi * TT + p0] = 2 * t;
        int p1 = atomicAdd(&g_counts[bi2], 1);
        g_list[bi2 * TT + p1] = 2 * t + 1;
    }
}

// ---------------- combine (pre-accumulated) + residual + LN3 ----------------
__global__ void combine_ln_kernel(const float* __restrict__ x1,
                                  const float* __restrict__ acc,
                                  const float* __restrict__ gam,
                                  const float* __restrict__ bet,
                                  float* __restrict__ out)
{
    __shared__ float ssum[8], ssum2[8];
    __shared__ float smean, srstd;
    int t = blockIdx.x;
    const float4* xr = (const float4*)(x1 + (size_t)t * DD);
    const float4* ar = (const float4*)(acc + (size_t)t * DD);
    float4 a = xr[threadIdx.x];
    float4 c0 = ar[threadIdx.x];
    float4 vv;
    vv.x = a.x + c0.x;
    vv.y = a.y + c0.y;
    vv.z = a.z + c0.z;
    vv.w = a.w + c0.w;
    float s = vv.x + vv.y + vv.z + vv.w;
    float s2 = vv.x * vv.x + vv.y * vv.y + vv.z * vv.z + vv.w * vv.w;
    int lane = threadIdx.x & 31, w = threadIdx.x >> 5;
#pragma unroll
    for (int o = 16; o; o >>= 1) {
        s += __shfl_xor_sync(~0u, s, o);
        s2 += __shfl_xor_sync(~0u, s2, o);
    }
    if (!lane) { ssum[w] = s; ssum2[w] = s2; }
    __syncthreads();
    if (threadIdx.x == 0) {
        float aa = 0.f, bb = 0.f;
#pragma unroll
        for (int i = 0; i < 8; i++) { aa += ssum[i]; bb += ssum2[i]; }
        float mean = aa * (1.f / DD);
        float var = bb * (1.f / DD) - mean * mean;
        smean = mean; srstd = rsqrtf(var + 1e-5f);
    }
    __syncthreads();
    float4 g4 = ((const float4*)gam)[threadIdx.x];
    float4 b4 = ((const float4*)bet)[threadIdx.x];
    float m = smean, rs = srstd;
    float4 o4;
    o4.x = (vv.x - m) * rs * g4.x + b4.x;
    o4.y = (vv.y - m) * rs * g4.y + b4.y;
    o4.z = (vv.z - m) * rs * g4.z + b4.z;
    o4.w = (vv.w - m) * rs * g4.w + b4.w;
    ((float4*)(out + (size_t)t * DD))[threadIdx.x] = o4;
}

// ---------------- launch ----------------
extern "C" void kernel_launch(void* const* d_in, const int* in_sizes, int n_in,
                              void* d_out, int out_size)
{
    const float* x    = (const float*)d_in[0];
    const float* Wq   = (const float*)d_in[1];
    const float* bq   = (const float*)d_in[2];
    const float* Wk   = (const float*)d_in[3];
    const float* bk   = (const float*)d_in[4];
    const float* Wv   = (const float*)d_in[5];
    const float* bv   = (const float*)d_in[6];
    const float* Wo   = (const float*)d_in[7];
    const float* bo   = (const float*)d_in[8];
    const float* ln1g = (const float*)d_in[9];
    const float* ln1b = (const float*)d_in[10];
    const float* gw   = (const float*)d_in[11];
    const float* gb   = (const float*)d_in[12];
    const float* W1   = (const float*)d_in[13];
    const float* b1   = (const float*)d_in[14];
    const float* W2   = (const float*)d_in[15];
    const float* b2   = (const float*)d_in[16];
    const float* ln3g = (const float*)d_in[17];
    const float* ln3b = (const float*)d_in[18];
    float* out = (float*)d_out;

    static int attr_set = 0;
    static cudaStream_t s2;
    static cudaEvent_t evFork, evWo, evJoin;
    if (!attr_set) {
        cudaFuncSetAttribute(mm_half_split, cudaFuncAttributeMaxDynamicSharedMemorySize, SPLIT_SMEM);
        cudaFuncSetAttribute(mm_half_plain, cudaFuncAttributeMaxDynamicSharedMemorySize, PLAIN_SMEM);
        cudaFuncSetAttribute(attn_half_kernel, cudaFuncAttributeMaxDynamicSharedMemorySize, ATTN_SMEM);
        cudaStreamCreateWithFlags(&s2, cudaStreamNonBlocking);
        cudaEventCreateWithFlags(&evFork, cudaEventDisableTiming);
        cudaEventCreateWithFlags(&evWo, cudaEventDisableTiming);
        cudaEventCreateWithFlags(&evJoin, cudaEventDisableTiming);
        attr_set = 1;
    }

    uint2 *pxhl, *pwqkvhl, *pwohl, *pqkhl, *pvhl, *pcthl;
    uint32_t *px1h, *pw1h, *pw2h, *pacth;
    float *pv, *pres1, *px1, *pacc, *pbqkv, *pgatew;
    int *pcounts, *plist;
    cudaGetSymbolAddress((void**)&pxhl, g_xhl);
    cudaGetSymbolAddress((void**)&pwqkvhl, g_wqkvhl);
    cudaGetSymbolAddress((void**)&pwohl, g_wohl);
    cudaGetSymbolAddress((void**)&pqkhl, g_qkhl);
    cudaGetSymbolAddress((void**)&pv, g_v);
    cudaGetSymbolAddress((void**)&pvhl, g_vhl);
    cudaGetSymbolAddress((void**)&pcthl, g_cthl);
    cudaGetSymbolAddress((void**)&pres1, g_res1);
    cudaGetSymbolAddress((void**)&px1, g_x1);
    cudaGetSymbolAddress((void**)&px1h, g_x1h);
    cudaGetSymbolAddress((void**)&pw1h, g_w1h);
    cudaGetSymbolAddress((void**)&pw2h, g_w2h);
    cudaGetSymbolAddress((void**)&pacth, g_acth);
    cudaGetSymbolAddress((void**)&pacc, g_acc);
    cudaGetSymbolAddress((void**)&pgatew, g_gatew);
    cudaGetSymbolAddress((void**)&pbqkv, g_bqkv);
    cudaGetSymbolAddress((void**)&pcounts, g_counts);
    cudaGetSymbolAddress((void**)&plist, g_list);

    // ---- fork side stream: Wo/W1/W2 packs + acc zero ----
    cudaEventRecord(evFork, 0);
    cudaStreamWaitEvent(s2, evFork, 0);
    pack_rows2i_kernel<<<128, 256, 0, s2>>>(Wo, pwohl, 10, DP * DD);
    cudaEventRecord(evWo, s2);
    pack_rows2_kernel<<<4096, 256, 0, s2>>>(W1, pw1h, 12, EE * DP * FF);
    pack_rows2_kernel<<<4096, 256, 0, s2>>>(W2, pw2h, 10, EE * (FF / 2) * DD);
    zero_acc_kernel<<<TT * DD / 1024, 256, 0, s2>>>(pacc);
    cudaEventRecord(evJoin, s2);

    // ---- main stream ----
    pack_cols_kernel<<<TT, 256>>>(x, pxhl);
    pack_rows2i_kernel<<<128, 256>>>(Wq, pwqkvhl, 10, DP * DD);
    pack_rows2i_kernel<<<128, 256>>>(Wk, pwqkvhl + DP * DD, 10, DP * DD);
    pack_rows2i_kernel<<<128, 256>>>(Wv, pwqkvhl + 2 * DP * DD, 10, DP * DD);
    concat_bias_kernel<<<4, 256>>>(bq, bk, bv, pbqkv);

    // QKV: z0->Q packed, z1->K packed, z2->V fp32
    mm_half_split<<<dim3(DD / 128, TT / 128, 3), 256, SPLIT_SMEM>>>(
        pxhl, pwqkvhl, pbqkv, nullptr, pqkhl, pv, DD, DD, 2);

    pack_rows2i_kernel<<<512, 256>>>(pv, pvhl, 10, (TT / 2) * DD);

    // attention
    attn_half_kernel<<<dim3(SS / 64, HH, 2), 256, ATTN_SMEM>>>(
        pqkhl, pqkhl + (size_t)TT * DP, pvhl, pcthl);

    // join: Wo pack ready before O-projection
    cudaStreamWaitEvent(0, evWo, 0);
    mm_half_split<<<dim3(DD / 128, TT / 128, 1), 256, SPLIT_SMEM>>>(
        pcthl, pwohl, bo, x, nullptr, pres1, DD, DD, 0);

    ln_kernel<<<TT, 256>>>(pres1, ln1g, ln1b, px1, px1h);

    zero_counts_kernel<<<1, 32>>>();
    gate_kernel<<<TT / 8, 256>>>(px1, gw, gb);

    // join: W1/W2 packs + acc zero ready before FFN
    cudaStreamWaitEvent(0, evJoin, 0);

    mm_half_plain<<<dim3(FF / 128, TT / 128, EE), 256, PLAIN_SMEM>>>(
        px1h, pw1h, b1, pacth, nullptr, nullptr, DD, FF, plist, pcounts, 1, 3);

    mm_half_plain<<<dim3(DD / 128, TT / 128, EE), 256, PLAIN_SMEM>>>(
        pacth, pw2h, b2, nullptr, pacc, pgatew, FF, DD, plist, pcounts, 0, 0);

    combine_ln_kernel<<<TT, 256>>>(px1, pacc, ln3g, ln3b, out);
}

// round 16
// speedup vs baseline: 1.0667x; 1.0667x over previous
#include <cuda_runtime.h>
#include <cuda_fp16.h>
#include <math.h>
#include <stdint.h>

#define TT 4096
#define DD 1024
#define FF 4096
#define EE 8
#define SS 2048
#define HH 16
#define DK 64
#define DP (DD/2)

// ---------------- scratch ----------------
__device__ uint32_t g_xh[TT * DP], g_xl[TT * DP];
__device__ uint32_t g_wqkvh[3u * DP * DD], g_wqkvl[3u * DP * DD]; // [z][K/2][N]
__device__ uint32_t g_woh[DP * DD], g_wol[DP * DD];
__device__ uint32_t g_qkh[2u * TT * DP], g_qkl[2u * TT * DP];
__device__ float    g_v[TT * DD];
__device__ uint32_t g_vh[(TT / 2) * DD], g_vl[(TT / 2) * DD];
__device__ uint32_t g_cth[TT * DP], g_ctl[TT * DP];
__device__ float    g_res1[TT * DD];
__device__ float    g_x1[TT * DD];
__device__ uint32_t g_x1h[TT * DP];
__device__ uint32_t g_w1h[(size_t)EE * DP * FF];          // [E][D/2][F]
__device__ uint32_t g_w2h[(size_t)EE * (FF / 2) * DD];    // [E][F/2][D]
__device__ uint32_t g_acth[2u * TT * (FF / 2)];
__device__ float    g_acc[TT * DD];
__device__ float    g_gatew[2 * TT];
__device__ int      g_counts[EE];
__device__ int      g_list[EE * TT];
__device__ float    g_bqkv[3 * DD];

// ---------------- helpers ----------------
__device__ __forceinline__ uint32_t smem_u32(const void* p) {
    uint32_t a;
    asm("{ .reg .u64 t; cvta.to.shared.u64 t, %1; cvt.u32.u64 %0, t; }" : "=r"(a) : "l"(p));
    return a;
}
__device__ __forceinline__ void cp16(uint32_t dst, const void* src) {
    asm volatile("cp.async.cg.shared.global [%0], [%1], 16;" :: "r"(dst), "l"(src));
}
__device__ __forceinline__ void cp16z(uint32_t dst, const void* src, int sz) {
    asm volatile("cp.async.cg.shared.global [%0], [%1], 16, %2;" :: "r"(dst), "l"(src), "r"(sz));
}
__device__ __forceinline__ void cp_commit() { asm volatile("cp.async.commit_group;"); }
__device__ __forceinline__ void cp_wait1() { asm volatile("cp.async.wait_group 1;" ::: "memory"); }
__device__ __forceinline__ void cp_wait0() { asm volatile("cp.async.wait_group 0;" ::: "memory"); }

__device__ __forceinline__ void mma_f16(float* d, const uint32_t* a, const uint32_t* b) {
    asm volatile(
        "mma.sync.aligned.m16n8k16.row.col.f32.f16.f16.f32 "
        "{%0,%1,%2,%3}, {%4,%5,%6,%7}, {%8,%9}, {%0,%1,%2,%3};"
        : "+f"(d[0]), "+f"(d[1]), "+f"(d[2]), "+f"(d[3])
        : "r"(a[0]), "r"(a[1]), "r"(a[2]), "r"(a[3]), "r"(b[0]), "r"(b[1]));
}
__device__ __forceinline__ uint32_t packh2(float a, float b) {
    __half2 h = __floats2half2_rn(a, b);
    return *reinterpret_cast<uint32_t*>(&h);
}
__device__ __forceinline__ void split2(float a, float b, uint32_t& hi, uint32_t& lo) {
    __half2 h = __floats2half2_rn(a, b);
    float2 f = __half22float2(h);
    __half2 l = __floats2half2_rn(a - f.x, b - f.y);
    hi = *reinterpret_cast<uint32_t*>(&h);
    lo = *reinterpret_cast<uint32_t*>(&l);
}
__device__ __forceinline__ float fexp(float x) {
    float t = fmaxf(x * 1.4426950408889634f, -126.0f);
    float fl = floorf(t);
    float f = t - fl;
    float p = 1.53998500e-4f;
    p = fmaf(p, f, 1.33335581e-3f);
    p = fmaf(p, f, 9.61817007e-3f);
    p = fmaf(p, f, 5.55041087e-2f);
    p = fmaf(p, f, 2.40226507e-1f);
    p = fmaf(p, f, 6.93147182e-1f);
    p = fmaf(p, f, 1.0f);
    return __int_as_float(__float_as_int(p) + (((int)fl) << 23));
}

// ---------------- pack kernels ----------------
__global__ void pack_rows2_kernel(const float* __restrict__ in, uint32_t* __restrict__ oh,
                                  uint32_t* __restrict__ ol, int shift, int total)
{
    int t0 = (blockIdx.x * 256 + threadIdx.x) * 4;
    int stride = gridDim.x * 1024;
    int C = 1 << shift;
    float4 a[4], b[4];
#pragma unroll
    for (int u = 0; u < 4; u++) {
        int i = t0 + u * stride;
        size_t ai = (size_t)i + ((size_t)(i >> shift) << shift);
        a[u] = *(const float4*)(in + ai);
        b[u] = *(const float4*)(in + ai + C);
    }
    if (ol) {
#pragma unroll
        for (int u = 0; u < 4; u++) {
            int i = t0 + u * stride;
            uint32_t h, l;
            split2(a[u].x, b[u].x, h, l); oh[i + 0] = h; ol[i + 0] = l;
            split2(a[u].y, b[u].y, h, l); oh[i + 1] = h; ol[i + 1] = l;
            split2(a[u].z, b[u].z, h, l); oh[i + 2] = h; ol[i + 2] = l;
            split2(a[u].w, b[u].w, h, l); oh[i + 3] = h; ol[i + 3] = l;
        }
    } else {
#pragma unroll
        for (int u = 0; u < 4; u++) {
            int i = t0 + u * stride;
            oh[i + 0] = packh2(a[u].x, b[u].x);
            oh[i + 1] = packh2(a[u].y, b[u].y);
            oh[i + 2] = packh2(a[u].z, b[u].z);
            oh[i + 3] = packh2(a[u].w, b[u].w);
        }
    }
}

__global__ void pack_cols_kernel(const float* __restrict__ in, uint32_t* __restrict__ oh,
                                 uint32_t* __restrict__ ol)
{
    int r = blockIdx.x;
    int c = threadIdx.x * 4;
    float4 a = *(const float4*)(in + (size_t)r * DD + c);
    uint32_t h0, l0, h1, l1;
    split2(a.x, a.y, h0, l0);
    split2(a.z, a.w, h1, l1);
    oh[(size_t)r * DP + (c >> 1)] = h0;
    oh[(size_t)r * DP + (c >> 1) + 1] = h1;
    ol[(size_t)r * DP + (c >> 1)] = l0;
    ol[(size_t)r * DP + (c >> 1) + 1] = l1;
}

__global__ void concat_bias_kernel(const float* bq, const float* bk, const float* bv,
                                   float* out)
{
    int i = blockIdx.x * 256 + threadIdx.x;
    if (i < DD) { out[i] = bq[i]; out[DD + i] = bk[i]; out[2 * DD + i] = bv[i]; }
}

__global__ void zero_acc_kernel(float* acc)
{
    ((float4*)acc)[blockIdx.x * 256 + threadIdx.x] = make_float4(0.f, 0.f, 0.f, 0.f);
}

// ========== fp16 2-way-split GEMM (fp32-faithful): QKV + O ==========
#define AP2 20
#define ASTG2 (128 * AP2)
#define BP2 136
#define BSTG2 (16 * BP2)
#define SPLIT_SMEM ((2 * 2 * ASTG2 + 2 * 2 * BSTG2) * 4)   // 75776 B

__global__ void __launch_bounds__(256)
mm_half_split(const uint32_t* __restrict__ Ah, const uint32_t* __restrict__ Al,
              const uint32_t* __restrict__ BhB, const uint32_t* __restrict__ BlB,
              const float* __restrict__ biasB,
              const float* __restrict__ resid,
              uint32_t* __restrict__ OHB, uint32_t* __restrict__ OLB,
              float* __restrict__ OF,
              int K, int N, int fp32z)
{
    int z = blockIdx.z;
    int m0 = blockIdx.y * 128;
    int n0 = blockIdx.x * 128;
    int Kp = K >> 1;
    const uint32_t* Bh = BhB + (size_t)z * Kp * N;
    const uint32_t* Bl = BlB + (size_t)z * Kp * N;
    const float* bias = biasB + (size_t)z * N;

    extern __shared__ uint32_t smu[];
    uint32_t* sAh = smu;
    uint32_t* sAl = smu + 2 * ASTG2;
    uint32_t* sBh = smu + 4 * ASTG2;
    uint32_t* sBl = smu + 4 * ASTG2 + 2 * BSTG2;
    uint32_t uAh = smem_u32(sAh), uAl = smem_u32(sAl);
    uint32_t uBh = smem_u32(sBh), uBl = smem_u32(sBl);

    int tid = threadIdx.x;

    auto load_stage = [&](int s, int kp0) {
#pragma unroll
        for (int i = 0; i < 8; i++) {
            int c = (tid + (i & 1) * 256) & 511;
            if (i < 4) {
                int row = c >> 2, seg = c & 3;
                const uint32_t* g = (i < 2) ? Ah : Al;
                uint32_t u = (i < 2) ? uAh : uAl;
                cp16(u + (uint32_t)(s * ASTG2 + row * AP2 + seg * 4) * 4,
                     g + (size_t)(m0 + row) * Kp + kp0 + seg * 4);
            } else {
                int prow = c >> 5, seg = c & 31;
                const uint32_t* g = (i < 6) ? Bh : Bl;
                uint32_t u = (i < 6) ? uBh : uBl;
                cp16(u + (uint32_t)(s * BSTG2 + prow * BP2 + seg * 4) * 4,
                     g + (size_t)(kp0 + prow) * N + n0 + seg * 4);
            }
        }
    };

    int NC = K >> 5;
    load_stage(0, 0); cp_commit();
    load_stage(1, 16); cp_commit();

    int w = tid >> 5, lane = tid & 31;
    int wm = w & 3, wn = w >> 2;
    int g = lane >> 2, ct = lane & 3;

    float acc[2][8][4];
#pragma unroll
    for (int mi = 0; mi < 2; mi++)
#pragma unroll
        for (int ni = 0; ni < 8; ni++)
#pragma unroll
            for (int j = 0; j < 4; j++) acc[mi][ni][j] = 0.f;

    for (int i = 0; i < NC; i++) {
        if (i + 1 < NC) cp_wait1(); else cp_wait0();
        __syncthreads();
        const uint32_t* Ahw = sAh + (i & 1) * ASTG2;
        const uint32_t* Alw = sAl + (i & 1) * ASTG2;
        const uint32_t* Bhw = sBh + (i & 1) * BSTG2;
        const uint32_t* Blw = sBl + (i & 1) * BSTG2;
#pragma unroll
        for (int ks = 0; ks < 2; ks++) {
            int kb = ks * 8;
            uint32_t ah[2][4], al[2][4];
#pragma unroll
            for (int mi = 0; mi < 2; mi++) {
                int rb = wm * 32 + mi * 16;
                ah[mi][0] = Ahw[(rb + g) * AP2 + kb + ct];
                ah[mi][1] = Ahw[(rb + g + 8) * AP2 + kb + ct];
                ah[mi][2] = Ahw[(rb + g) * AP2 + kb + ct + 4];
                ah[mi][3] = Ahw[(rb + g + 8) * AP2 + kb + ct + 4];
                al[mi][0] = Alw[(rb + g) * AP2 + kb + ct];
                al[mi][1] = Alw[(rb + g + 8) * AP2 + kb + ct];
                al[mi][2] = Alw[(rb + g) * AP2 + kb + ct + 4];
                al[mi][3] = Alw[(rb + g + 8) * AP2 + kb + ct + 4];
            }
#pragma unroll
            for (int ni = 0; ni < 8; ni++) {
                int n = wn * 64 + ni * 8 + g;
                uint32_t bh[2] = { Bhw[(kb + ct) * BP2 + n], Bhw[(kb + ct + 4) * BP2 + n] };
                uint32_t bl[2] = { Blw[(kb + ct) * BP2 + n], Blw[(kb + ct + 4) * BP2 + n] };
#pragma unroll
                for (int mi = 0; mi < 2; mi++) {
                    mma_f16(acc[mi][ni], ah[mi], bh);
                    mma_f16(acc[mi][ni], ah[mi], bl);
                    mma_f16(acc[mi][ni], al[mi], bh);
                }
            }
        }
        __syncthreads();
        if (i + 2 < NC) { load_stage(i & 1, (i + 2) * 16); cp_commit(); }
    }

    bool fp32o = (z == fp32z);
#pragma unroll
    for (int mi = 0; mi < 2; mi++) {
#pragma unroll
        for (int h = 0; h < 2; h++) {
            int m = m0 + wm * 32 + mi * 16 + g + h * 8;
#pragma unroll
            for (int ni = 0; ni < 8; ni++) {
                int col = n0 + wn * 64 + ni * 8 + 2 * ct;
                float v0 = acc[mi][ni][2 * h + 0] + bias[col];
                float v1 = acc[mi][ni][2 * h + 1] + bias[col + 1];
                if (fp32o) {
                    if (resid) {
                        v0 += resid[(size_t)m * N + col];
                        v1 += resid[(size_t)m * N + col + 1];
                    }
                    *(float2*)&OF[(size_t)m * N + col] = make_float2(v0, v1);
                } else {
                    uint32_t hh, ll;
                    split2(v0, v1, hh, ll);
                    size_t o = (size_t)z * TT * (N >> 1) + (size_t)m * (N >> 1) + (col >> 1);
                    OHB[o] = hh; OLB[o] = ll;
                }
            }
        }
    }
}

// ========== plain fp16 GEMM (gathered A) — 3-stage pipeline, 1 sync/chunk ====
#define PLAIN_SMEM ((3 * ASTG2 + 3 * BSTG2) * 4)   // 56832 B

__global__ void __launch_bounds__(256)
mm_half_plain(const uint32_t* __restrict__ Ah,
              const uint32_t* __restrict__ WhB,
              const float* __restrict__ biasB,
              uint32_t* __restrict__ OH,
              float* __restrict__ ACC,
              const float* __restrict__ gatew,
              int K, int N,
              const int* __restrict__ listB, const int* __restrict__ counts,
              int a_shift, int actmode)
{
    int e = blockIdx.z;
    const int* list = listB + e * TT;
    int Me = counts[e];
    int m0 = blockIdx.y * 128;
    if (m0 >= Me) return;
    int n0 = blockIdx.x * 128;
    int Kp = K >> 1;
    const uint32_t* Wh = WhB + (size_t)e * Kp * N;
    const float* bias = biasB + (size_t)e * N;

    extern __shared__ uint32_t smu[];
    uint32_t* sAh = smu;
    uint32_t* sBh = smu + 3 * ASTG2;
    uint32_t uAh = smem_u32(sAh), uBh = smem_u32(sBh);

    __shared__ int rows_s[128];
    __shared__ int crows_s[128];
    int tid = threadIdx.x;
    if (tid < 128) {
        int m = m0 + tid;
        int r = -1, cr = -1;
        if (m < Me) { int ent = list[m]; r = ent >> a_shift; cr = ent; }
        rows_s[tid] = r; crows_s[tid] = cr;
    }
    __syncthreads();

    auto load_stage = [&](int s, int kp0) {
#pragma unroll
        for (int i = 0; i < 4; i++) {
            int c = (tid + (i & 1) * 256) & 511;
            if (i < 2) {
                int row = c >> 2, seg = c & 3;
                int ar = rows_s[row];
                const uint32_t* src = (ar >= 0) ? Ah + (size_t)ar * Kp + kp0 + seg * 4 : Ah;
                cp16z(uAh + (uint32_t)(s * ASTG2 + row * AP2 + seg * 4) * 4, src,
                      (ar >= 0) ? 16 : 0);
            } else {
                int prow = c >> 5, seg = c & 31;
                cp16(uBh + (uint32_t)(s * BSTG2 + prow * BP2 + seg * 4) * 4,
                     Wh + (size_t)(kp0 + prow) * N + n0 + seg * 4);
            }
        }
    };

    int NC = K >> 5;
    load_stage(0, 0); cp_commit();
    load_stage(1, 16); cp_commit();

    int w = tid >> 5, lane = tid & 31;
    int wm = w & 3, wn = w >> 2;
    int g = lane >> 2, ct = lane & 3;

    float acc[2][8][4];
#pragma unroll
    for (int mi = 0; mi < 2; mi++)
#pragma unroll
        for (int ni = 0; ni < 8; ni++)
#pragma unroll
            for (int j = 0; j < 4; j++) acc[mi][ni][j] = 0.f;

    for (int i = 0; i < NC; i++) {
        if (i + 1 < NC) cp_wait1(); else cp_wait0();
        __syncthreads();
        if (i + 2 < NC) { load_stage((i + 2) % 3, (i + 2) * 16); cp_commit(); }
        int sb = i % 3;
        const uint32_t* Ahw = sAh + sb * ASTG2;
        const uint32_t* Bhw = sBh + sb * BSTG2;
#pragma unroll
        for (int ks = 0; ks < 2; ks++) {
            int kb = ks * 8;
            uint32_t ah[2][4];
#pragma unroll
            for (int mi = 0; mi < 2; mi++) {
                int rb = wm * 32 + mi * 16;
                ah[mi][0] = Ahw[(rb + g) * AP2 + kb + ct];
                ah[mi][1] = Ahw[(rb + g + 8) * AP2 + kb + ct];
                ah[mi][2] = Ahw[(rb + g) * AP2 + kb + ct + 4];
                ah[mi][3] = Ahw[(rb + g + 8) * AP2 + kb + ct + 4];
            }
#pragma unroll
            for (int ni = 0; ni < 8; ni++) {
                int n = wn * 64 + ni * 8 + g;
                uint32_t bh[2] = { Bhw[(kb + ct) * BP2 + n], Bhw[(kb + ct + 4) * BP2 + n] };
#pragma unroll
                for (int mi = 0; mi < 2; mi++)
                    mma_f16(acc[mi][ni], ah[mi], bh);
            }
        }
    }

    int act = (actmode == 3) ? ((e & 1) ? 2 : 1) : actmode;
#pragma unroll
    for (int mi = 0; mi < 2; mi++) {
#pragma unroll
        for (int h = 0; h < 2; h++) {
            int rl = wm * 32 + mi * 16 + g + h * 8;
            int crow = crows_s[rl];
            if (crow < 0) continue;
            float wgt = OH ? 0.f : gatew[crow];
#pragma unroll
            for (int ni = 0; ni < 8; ni++) {
                int col = n0 + wn * 64 + ni * 8 + 2 * ct;
                float v0 = acc[mi][ni][2 * h + 0] + bias[col];
                float v1 = acc[mi][ni][2 * h + 1] + bias[col + 1];
                if (act == 1) {
                    v0 = 0.5f * v0 * (1.f + erff(v0 * 0.70710678118654752f));
                    v1 = 0.5f * v1 * (1.f + erff(v1 * 0.70710678118654752f));
                } else if (act == 2) {
                    v0 = v0 / (1.f + __expf(-v0));
                    v1 = v1 / (1.f + __expf(-v1));
                }
                if (OH) {
                    OH[(size_t)crow * (N >> 1) + (col >> 1)] = packh2(v0, v1);
                } else {
                    float* arow = ACC + (size_t)(crow >> 1) * N + col;
                    atomicAdd(arow, wgt * v0);
                    atomicAdd(arow + 1, wgt * v1);
                }
            }
        }
    }
}

// ========== fp16-split flash attention (round-7 layout, Q frags hoisted) =====
#define QOFF 0
#define QLOFF 2304
#define KOFF 4608
#define KLOFF 6912
#define VOFF 9216
#define VLOFF 11520
#define POFF 13824
#define PLOFF 16128
#define ATTN_SMEM (18432 * 4)

__global__ void __launch_bounds__(256, 2)
attn_half_kernel(const uint32_t* __restrict__ Qh, const uint32_t* __restrict__ Ql,
                 const uint32_t* __restrict__ Kh, const uint32_t* __restrict__ Kl,
                 const uint32_t* __restrict__ Vh, const uint32_t* __restrict__ Vl,
                 uint32_t* __restrict__ Ch, uint32_t* __restrict__ Cl)
{
    extern __shared__ uint32_t smu[];
    __shared__ float redm[128], reds[128];

    int qt = blockIdx.x, h = blockIdx.y, b = blockIdx.z;
    int tid = threadIdx.x;
    int w = tid >> 5, lane = tid & 31;
    int wm = w & 3, wn = w >> 2;
    int g = lane >> 2, ct = lane & 3;
    int r0 = wm * 16 + g, r1 = r0 + 8;

    int qglob = b * SS + qt * 64;

#pragma unroll
    for (int i = 0; i < 4; i++) {
        int c = tid + i * 256;
        int plane = c >> 9, cc = c & 511;
        int row = cc >> 3, seg = cc & 7;
        const uint32_t* src = plane ? Ql : Qh;
        uint32_t dst = smem_u32(smu + (plane ? QLOFF : QOFF));
        cp16(dst + (uint32_t)(row * 36 + seg * 4) * 4,
             src + (size_t)(qglob + row) * DP + h * 32 + seg * 4);
    }
    cp_commit();

    float oacc[4][4];
#pragma unroll
    for (int ni = 0; ni < 4; ni++)
#pragma unroll
        for (int j = 0; j < 4; j++) oacc[ni][j] = 0.f;
    float mrun0 = -1e30f, mrun1 = -1e30f, lrun0 = 0.f, lrun1 = 0.f;

    const uint32_t* Qhs = smu + QOFF;  const uint32_t* Qls = smu + QLOFF;
    const uint32_t* Khs = smu + KOFF;  const uint32_t* Kls = smu + KLOFF;
    const uint32_t* Vhs = smu + VOFF;  const uint32_t* Vls = smu + VLOFF;
    uint32_t* Phs = smu + POFF;        uint32_t* Pls = smu + PLOFF;

    // hoist Q fragments into registers (loop-invariant across all KV tiles)
    cp_wait0();
    __syncthreads();
    uint32_t qah[4][4], qal[4][4];
#pragma unroll
    for (int ks = 0; ks < 4; ks++) {
        int kb = ks * 8;
        qah[ks][0] = Qhs[r0 * 36 + kb + ct];
        qah[ks][1] = Qhs[r1 * 36 + kb + ct];
        qah[ks][2] = Qhs[r0 * 36 + kb + ct + 4];
        qah[ks][3] = Qhs[r1 * 36 + kb + ct + 4];
        qal[ks][0] = Qls[r0 * 36 + kb + ct];
        qal[ks][1] = Qls[r1 * 36 + kb + ct];
        qal[ks][2] = Qls[r0 * 36 + kb + ct + 4];
        qal[ks][3] = Qls[r1 * 36 + kb + ct + 4];
    }

    for (int t = 0; t < SS / 64; t++) {
        int k0t = t * 64;
        __syncthreads();
#pragma unroll
        for (int i = 0; i < 4; i++) {
            int c = tid + i * 256;
            int plane = c >> 9, cc = c & 511;
            int row = cc >> 3, seg = cc & 7;
            const uint32_t* src = plane ? Kl : Kh;
            uint32_t dst = smem_u32(smu + (plane ? KLOFF : KOFF));
            cp16(dst + (uint32_t)(row * 36 + seg * 4) * 4,
                 src + (size_t)(b * SS + k0t + row) * DP + h * 32 + seg * 4);
        }
#pragma unroll
        for (int i = 0; i < 4; i++) {
            int c = tid + i * 256;
            int plane = c >> 9, cc = c & 511;
            int row = cc >> 4, seg = cc & 15;
            const uint32_t* src = plane ? Vl : Vh;
            uint32_t dst = smem_u32(smu + (plane ? VLOFF : VOFF));
            cp16(dst + (uint32_t)(row * 72 + seg * 4) * 4,
                 src + (size_t)((b * SS + k0t) / 2 + row) * DD + h * 64 + seg * 4);
        }
        cp_commit();
        cp_wait0();
        __syncthreads();

        // ---- S = Q K^T (fp16 split, Q frags in registers) ----
        float sacc[4][4];
#pragma unroll
        for (int ni = 0; ni < 4; ni++)
#pragma unroll
            for (int j = 0; j < 4; j++) sacc[ni][j] = 0.f;
#pragma unroll
        for (int ks = 0; ks < 4; ks++) {
            int kb = ks * 8;
#pragma unroll
            for (int ni = 0; ni < 4; ni++) {
                int n = wn * 32 + ni * 8 + g;
                uint32_t bh[2] = { Khs[n * 36 + kb + ct], Khs[n * 36 + kb + ct + 4] };
                uint32_t bl[2] = { Kls[n * 36 + kb + ct], Kls[n * 36 + kb + ct + 4] };
                mma_f16(sacc[ni], qah[ks], bh);
                mma_f16(sacc[ni], qah[ks], bl);
                mma_f16(sacc[ni], qal[ks], bh);
            }
        }
#pragma unroll
        for (int ni = 0; ni < 4; ni++)
#pragma unroll
            for (int j = 0; j < 4; j++) sacc[ni][j] *= 0.125f;

        // ---- online softmax ----
        float mx0 = -1e30f, mx1 = -1e30f;
#pragma unroll
        for (int ni = 0; ni < 4; ni++) {
            mx0 = fmaxf(mx0, fmaxf(sacc[ni][0], sacc[ni][1]));
            mx1 = fmaxf(mx1, fmaxf(sacc[ni][2], sacc[ni][3]));
        }
        mx0 = fmaxf(mx0, __shfl_xor_sync(~0u, mx0, 1));
        mx0 = fmaxf(mx0, __shfl_xor_sync(~0u, mx0, 2));
        mx1 = fmaxf(mx1, __shfl_xor_sync(~0u, mx1, 1));
        mx1 = fmaxf(mx1, __shfl_xor_sync(~0u, mx1, 2));
        if (ct == 0) { redm[wn * 64 + r0] = mx0; redm[wn * 64 + r1] = mx1; }
        __syncthreads();
        float mn0 = fmaxf(mrun0, fmaxf(redm[r0], redm[64 + r0]));
        float mn1 = fmaxf(mrun1, fmaxf(redm[r1], redm[64 + r1]));
        float c0 = fexp(mrun0 - mn0), c1 = fexp(mrun1 - mn1);
        mrun0 = mn0; mrun1 = mn1;
        float sum0 = 0.f, sum1 = 0.f;
#pragma unroll
        for (int ni = 0; ni < 4; ni++) {
            float p00 = fexp(sacc[ni][0] - mn0), p01 = fexp(sacc[ni][1] - mn0);
            float p10 = fexp(sacc[ni][2] - mn1), p11 = fexp(sacc[ni][3] - mn1);
            sum0 += p00 + p01; sum1 += p10 + p11;
            int pc = wn * 16 + ni * 4 + ct;
            uint32_t hh, ll;
            split2(p00, p01, hh, ll);
            Phs[r0 * 36 + pc] = hh; Pls[r0 * 36 + pc] = ll;
            split2(p10, p11, hh, ll);
            Phs[r1 * 36 + pc] = hh; Pls[r1 * 36 + pc] = ll;
        }
        sum0 += __shfl_xor_sync(~0u, sum0, 1);
        sum0 += __shfl_xor_sync(~0u, sum0, 2);
        sum1 += __shfl_xor_sync(~0u, sum1, 1);
        sum1 += __shfl_xor_sync(~0u, sum1, 2);
        if (ct == 0) { reds[wn * 64 + r0] = sum0; reds[wn * 64 + r1] = sum1; }
        __syncthreads();
        lrun0 = lrun0 * c0 + reds[r0] + reds[64 + r0];
        lrun1 = lrun1 * c1 + reds[r1] + reds[64 + r1];
#pragma unroll
        for (int ni = 0; ni < 4; ni++) {
            oacc[ni][0] *= c0; oacc[ni][1] *= c0;
            oacc[ni][2] *= c1; oacc[ni][3] *= c1;
        }

        // ---- O += P V (fp16 split) ----
#pragma unroll
        for (int ks = 0; ks < 4; ks++) {
            int kb = ks * 8;
            uint32_t ah[4] = { Phs[r0 * 36 + kb + ct], Phs[r1 * 36 + kb + ct],
                               Phs[r0 * 36 + kb + ct + 4], Phs[r1 * 36 + kb + ct + 4] };
            uint32_t al[4] = { Pls[r0 * 36 + kb + ct], Pls[r1 * 36 + kb + ct],
                               Pls[r0 * 36 + kb + ct + 4], Pls[r1 * 36 + kb + ct + 4] };
#pragma unroll
            for (int ni = 0; ni < 4; ni++) {
                int n = wn * 32 + ni * 8 + g;
                uint32_t bh[2] = { Vhs[(kb + ct) * 72 + n], Vhs[(kb + ct + 4) * 72 + n] };
                uint32_t bl[2] = { Vls[(kb + ct) * 72 + n], Vls[(kb + ct + 4) * 72 + n] };
                mma_f16(oacc[ni], ah, bh);
                mma_f16(oacc[ni], ah, bl);
                mma_f16(oacc[ni], al, bh);
            }
        }
    }

    float inv0 = 1.f / lrun0, inv1 = 1.f / lrun1;
#pragma unroll
    for (int ni = 0; ni < 4; ni++) {
        int pc = h * 32 + wn * 16 + ni * 4 + ct;
        uint32_t hh, ll;
        size_t o0 = (size_t)(qglob + r0) * DP + pc;
        split2(oacc[ni][0] * inv0, oacc[ni][1] * inv0, hh, ll);
        Ch[o0] = hh; Cl[o0] = ll;
        size_t o1 = (size_t)(qglob + r1) * DP + pc;
        split2(oacc[ni][2] * inv1, oacc[ni][3] * inv1, hh, ll);
        Ch[o1] = hh; Cl[o1] = ll;
    }
}

// ---------------- layernorm ----------------
__global__ void ln_kernel(const float* __restrict__ in,
                          const float* __restrict__ gam,
                          const float* __restrict__ bet,
                          float* __restrict__ out, uint32_t* __restrict__ outh)
{
    __shared__ float ssum[8], ssum2[8];
    __shared__ float smean, srstd;
    int t = blockIdx.x;
    const float4* r = (const float4*)(in + (size_t)t * DD);
    float4 vv = r[threadIdx.x];
    float s = vv.x + vv.y + vv.z + vv.w;
    float s2 = vv.x * vv.x + vv.y * vv.y + vv.z * vv.z + vv.w * vv.w;
    int lane = threadIdx.x & 31, w = threadIdx.x >> 5;
#pragma unroll
    for (int o = 16; o; o >>= 1) {
        s += __shfl_xor_sync(~0u, s, o);
        s2 += __shfl_xor_sync(~0u, s2, o);
    }
    if (!lane) { ssum[w] = s; ssum2[w] = s2; }
    __syncthreads();
    if (threadIdx.x == 0) {
        float a = 0.f, bb = 0.f;
#pragma unroll
        for (int i = 0; i < 8; i++) { a += ssum[i]; bb += ssum2[i]; }
        float mean = a * (1.f / DD);
        float var = bb * (1.f / DD) - mean * mean;
        smean = mean; srstd = rsqrtf(var + 1e-5f);
    }
    __syncthreads();
    float4 g4 = ((const float4*)gam)[threadIdx.x];
    float4 b4 = ((const float4*)bet)[threadIdx.x];
    float m = smean, rs = srstd;
    float4 o4;
    o4.x = (vv.x - m) * rs * g4.x + b4.x;
    o4.y = (vv.y - m) * rs * g4.y + b4.y;
    o4.z = (vv.z - m) * rs * g4.z + b4.z;
    o4.w = (vv.w - m) * rs * g4.w + b4.w;
    ((float4*)(out + (size_t)t * DD))[threadIdx.x] = o4;
    if (outh) {
        outh[(size_t)t * DP + threadIdx.x * 2] = packh2(o4.x, o4.y);
        outh[(size_t)t * DP + threadIdx.x * 2 + 1] = packh2(o4.z, o4.w);
    }
}

// ---------------- gate ----------------
__global__ void zero_counts_kernel() {
    if (threadIdx.x < EE) g_counts[threadIdx.x] = 0;
}

__global__ void gate_kernel(const float* __restrict__ x1,
                            const float* __restrict__ gw,
                            const float* __restrict__ gb)
{
    int t = blockIdx.x * (blockDim.x / 32) + (threadIdx.x >> 5);
    int lane = threadIdx.x & 31;
    float acc[EE] = {};
    const float* xr = x1 + (size_t)t * DD;
    for (int d = lane; d < DD; d += 32) {
        float xv = xr[d];
        const float4* grow = (const float4*)(gw + (size_t)d * EE);
        float4 a0 = grow[0];
        float4 a1 = grow[1];
        acc[0] += xv * a0.x; acc[1] += xv * a0.y;
        acc[2] += xv * a0.z; acc[3] += xv * a0.w;
        acc[4] += xv * a1.x; acc[5] += xv * a1.y;
        acc[6] += xv * a1.z; acc[7] += xv * a1.w;
    }
#pragma unroll
    for (int e = 0; e < EE; e++)
#pragma unroll
        for (int o = 16; o; o >>= 1) acc[e] += __shfl_xor_sync(~0u, acc[e], o);
    if (lane == 0) {
#pragma unroll
        for (int e = 0; e < EE; e++) acc[e] += gb[e];
        float best = -1e30f; int bi = 0;
#pragma unroll
        for (int e = 0; e < EE; e++)
            if (acc[e] > best) { best = acc[e]; bi = e; }
        float best2 = -1e30f; int bi2 = 0;
#pragma unroll
        for (int e = 0; e < EE; e++)
            if (e != bi && acc[e] > best2) { best2 = acc[e]; bi2 = e; }
        float w0 = 1.f / (1.f + __expf(best2 - best));
        g_gatew[2 * t] = w0;
        g_gatew[2 * t + 1] = 1.f - w0;
        int p0 = atomicAdd(&g_counts[bi], 1);
        g_list[bi * TT + p0] = 2 * t;
        int p1 = atomicAdd(&g_counts[bi2], 1);
        g_list[bi2 * TT + p1] = 2 * t + 1;
    }
}

// ---------------- combine (pre-accumulated) + residual + LN3 ----------------
__global__ void combine_ln_kernel(const float* __restrict__ x1,
                                  const float* __restrict__ acc,
                                  const float* __restrict__ gam,
                                  const float* __restrict__ bet,
                                  float* __restrict__ out)
{
    __shared__ float ssum[8], ssum2[8];
    __shared__ float smean, srstd;
    int t = blockIdx.x;
    const float4* xr = (const float4*)(x1 + (size_t)t * DD);
    const float4* ar = (const float4*)(acc + (size_t)t * DD);
    float4 a = xr[threadIdx.x];
    float4 c0 = ar[threadIdx.x];
    float4 vv;
    vv.x = a.x + c0.x;
    vv.y = a.y + c0.y;
    vv.z = a.z + c0.z;
    vv.w = a.w + c0.w;
    float s = vv.x + vv.y + vv.z + vv.w;
    float s2 = vv.x * vv.x + vv.y * vv.y + vv.z * vv.z + vv.w * vv.w;
    int lane = threadIdx.x & 31, w = threadIdx.x >> 5;
#pragma unroll
    for (int o = 16; o; o >>= 1) {
        s += __shfl_xor_sync(~0u, s, o);
        s2 += __shfl_xor_sync(~0u, s2, o);
    }
    if (!lane) { ssum[w] = s; ssum2[w] = s2; }
    __syncthreads();
    if (threadIdx.x == 0) {
        float aa = 0.f, bb = 0.f;
#pragma unroll
        for (int i = 0; i < 8; i++) { aa += ssum[i]; bb += ssum2[i]; }
        float mean = aa * (1.f / DD);
        float var = bb * (1.f / DD) - mean * mean;
        smean = mean; srstd = rsqrtf(var + 1e-5f);
    }
    __syncthreads();
    float4 g4 = ((const float4*)gam)[threadIdx.x];
    float4 b4 = ((const float4*)bet)[threadIdx.x];
    float m = smean, rs = srstd;
    float4 o4;
    o4.x = (vv.x - m) * rs * g4.x + b4.x;
    o4.y = (vv.y - m) * rs * g4.y + b4.y;
    o4.z = (vv.z - m) * rs * g4.z + b4.z;
    o4.w = (vv.w - m) * rs * g4.w + b4.w;
    ((float4*)(out + (size_t)t * DD))[threadIdx.x] = o4;
}

// ---------------- launch ----------------
extern "C" void kernel_launch(void* const* d_in, const int* in_sizes, int n_in,
                              void* d_out, int out_size)
{
    const float* x    = (const float*)d_in[0];
    const float* Wq   = (const float*)d_in[1];
    const float* bq   = (const float*)d_in[2];
    const float* Wk   = (const float*)d_in[3];
    const float* bk   = (const float*)d_in[4];
    const float* Wv   = (const float*)d_in[5];
    const float* bv   = (const float*)d_in[6];
    const float* Wo   = (const float*)d_in[7];
    const float* bo   = (const float*)d_in[8];
    const float* ln1g = (const float*)d_in[9];
    const float* ln1b = (const float*)d_in[10];
    const float* gw   = (const float*)d_in[11];
    const float* gb   = (const float*)d_in[12];
    const float* W1   = (const float*)d_in[13];
    const float* b1   = (const float*)d_in[14];
    const float* W2   = (const float*)d_in[15];
    const float* b2   = (const float*)d_in[16];
    const float* ln3g = (const float*)d_in[17];
    const float* ln3b = (const float*)d_in[18];
    float* out = (float*)d_out;

    static int attr_set = 0;
    static cudaStream_t s2;
    static cudaEvent_t evFork, evWo, evJoin;
    if (!attr_set) {
        cudaFuncSetAttribute(mm_half_split, cudaFuncAttributeMaxDynamicSharedMemorySize, SPLIT_SMEM);
        cudaFuncSetAttribute(mm_half_plain, cudaFuncAttributeMaxDynamicSharedMemorySize, PLAIN_SMEM);
        cudaFuncSetAttribute(attn_half_kernel, cudaFuncAttributeMaxDynamicSharedMemorySize, ATTN_SMEM);
        cudaStreamCreateWithFlags(&s2, cudaStreamNonBlocking);
        cudaEventCreateWithFlags(&evFork, cudaEventDisableTiming);
        cudaEventCreateWithFlags(&evWo, cudaEventDisableTiming);
        cudaEventCreateWithFlags(&evJoin, cudaEventDisableTiming);
        attr_set = 1;
    }

    uint32_t *pxh, *pxl, *pwqkvh, *pwqkvl, *pwoh, *pwol, *pqkh, *pqkl;
    uint32_t *pvh, *pvl, *pcth, *pctl, *px1h, *pw1h, *pw2h, *pacth;
    float *pv, *pres1, *px1, *pacc, *pbqkv, *pgatew;
    int *pcounts, *plist;
    cudaGetSymbolAddress((void**)&pxh, g_xh);
    cudaGetSymbolAddress((void**)&pxl, g_xl);
    cudaGetSymbolAddress((void**)&pwqkvh, g_wqkvh);
    cudaGetSymbolAddress((void**)&pwqkvl, g_wqkvl);
    cudaGetSymbolAddress((void**)&pwoh, g_woh);
    cudaGetSymbolAddress((void**)&pwol, g_wol);
    cudaGetSymbolAddress((void**)&pqkh, g_qkh);
    cudaGetSymbolAddress((void**)&pqkl, g_qkl);
    cudaGetSymbolAddress((void**)&pv, g_v);
    cudaGetSymbolAddress((void**)&pvh, g_vh);
    cudaGetSymbolAddress((void**)&pvl, g_vl);
    cudaGetSymbolAddress((void**)&pcth, g_cth);
    cudaGetSymbolAddress((void**)&pctl, g_ctl);
    cudaGetSymbolAddress((void**)&pres1, g_res1);
    cudaGetSymbolAddress((void**)&px1, g_x1);
    cudaGetSymbolAddress((void**)&px1h, g_x1h);
    cudaGetSymbolAddress((void**)&pw1h, g_w1h);
    cudaGetSymbolAddress((void**)&pw2h, g_w2h);
    cudaGetSymbolAddress((void**)&pacth, g_acth);
    cudaGetSymbolAddress((void**)&pacc, g_acc);
    cudaGetSymbolAddress((void**)&pgatew, g_gatew);
    cudaGetSymbolAddress((void**)&pbqkv, g_bqkv);
    cudaGetSymbolAddress((void**)&pcounts, g_counts);
    cudaGetSymbolAddress((void**)&plist, g_list);

    // ---- fork side stream: Wo/W1/W2 packs + acc zero ----
    cudaEventRecord(evFork, 0);
    cudaStreamWaitEvent(s2, evFork, 0);
    pack_rows2_kernel<<<128, 256, 0, s2>>>(Wo, pwoh, pwol, 10, DP * DD);
    cudaEventRecord(evWo, s2);
    pack_rows2_kernel<<<4096, 256, 0, s2>>>(W1, pw1h, nullptr, 12, EE * DP * FF);
    pack_rows2_kernel<<<4096, 256, 0, s2>>>(W2, pw2h, nullptr, 10, EE * (FF / 2) * DD);
    zero_acc_kernel<<<TT * DD / 1024, 256, 0, s2>>>(pacc);
    cudaEventRecord(evJoin, s2);

    // ---- main stream ----
    pack_cols_kernel<<<TT, 256>>>(x, pxh, pxl);
    pack_rows2_kernel<<<128, 256>>>(Wq, pwqkvh, pwqkvl, 10, DP * DD);
    pack_rows2_kernel<<<128, 256>>>(Wk, pwqkvh + DP * DD, pwqkvl + DP * DD, 10, DP * DD);
    pack_rows2_kernel<<<128, 256>>>(Wv, pwqkvh + 2 * DP * DD, pwqkvl + 2 * DP * DD, 10, DP * DD);
    concat_bias_kernel<<<4, 256>>>(bq, bk, bv, pbqkv);

    // QKV (split fp16): z0->Q packed, z1->K packed, z2->V fp32
    mm_half_split<<<dim3(DD / 128, TT / 128, 3), 256, SPLIT_SMEM>>>(
        pxh, pxl, pwqkvh, pwqkvl, pbqkv, nullptr, pqkh, pqkl, pv, DD, DD, 2);

    pack_rows2_kernel<<<512, 256>>>(pv, pvh, pvl, 10, (TT / 2) * DD);

    // attention
    attn_half_kernel<<<dim3(SS / 64, HH, 2), 256, ATTN_SMEM>>>(
        pqkh, pqkl, pqkh + (size_t)TT * DP, pqkl + (size_t)TT * DP,
        pvh, pvl, pcth, pctl);

    // join: Wo pack ready before O-projection
    cudaStreamWaitEvent(0, evWo, 0);
    mm_half_split<<<dim3(DD / 128, TT / 128, 1), 256, SPLIT_SMEM>>>(
        pcth, pctl, pwoh, pwol, bo, x, nullptr, nullptr, pres1, DD, DD, 0);

    ln_kernel<<<TT, 256>>>(pres1, ln1g, ln1b, px1, px1h);

    zero_counts_kernel<<<1, 32>>>();
    gate_kernel<<<TT / 8, 256>>>(px1, gw, gb);

    // join: W1/W2 packs + acc zero ready before FFN
    cudaStreamWaitEvent(0, evJoin, 0);

    mm_half_plain<<<dim3(FF / 128, TT / 128, EE), 256, PLAIN_SMEM>>>(
        px1h, pw1h, b1, pacth, nullptr, nullptr, DD, FF, plist, pcounts, 1, 3);

    mm_half_plain<<<dim3(DD / 128, TT / 128, EE), 256, PLAIN_SMEM>>>(
        pacth, pw2h, b2, nullptr, pacc, pgatew, FF, DD, plist, pcounts, 0, 0);

    combine_ln_kernel<<<TT, 256>>>(px1, pacc, ln3g, ln3b, out);
}